// round 15
// baseline (speedup 1.0000x reference)
#include <cuda_runtime.h>
#include <cstdint>

#define PB 4
#define PN 16384
#define PS 2048
#define PC 64
#define PK 33
#define PNS 32
#define JTOT (PS * PK)        // 67584 = 512 * 132
#define OUTC (6 + PC)         // 70
#define GR 10
#define NC (GR * GR * GR)     // 1000
#define CAP 256
#define TJ 132                // 4 queries * 33 slots per block
#define BPBATCH 512           // fused blocks per batch
#define BCAP 96               // bucket capacity (Poisson(16.4); P(>96)~1e-18)

__device__ float4 g_featT4[(size_t)PB * PN * PC / 4];
__device__ int    g_cellCnt[PB * NC];               // zero-init; fused tail re-zeroes
__device__ float4 g_ptsB[(size_t)PB * NC * BCAP];   // padded per-cell buckets

__device__ __forceinline__ int cell_of(float x, float y, float z) {
    int ix = min((int)(x * 10.0f), GR - 1);
    int iy = min((int)(y * 10.0f), GR - 1);
    int iz = min((int)(z * 10.0f), GR - 1);
    return (iz * GR + iy) * GR + ix;
}

// ---------------------------------------------------------------------------
// Grid build: ONE pass. Direct scatter into padded buckets via atomic cursors.
// ---------------------------------------------------------------------------
__global__ void __launch_bounds__(256) scatter_direct(const float* __restrict__ xyz) {
    int i = blockIdx.x * 256 + threadIdx.x;           // 0..65535
    const float* p = xyz + 3 * (size_t)i;
    float x = p[0], y = p[1], z = p[2];
    int b = i >> 14;
    int n = i & (PN - 1);
    int cell = b * NC + cell_of(x, y, z);
    int pos = atomicAdd(&g_cellCnt[cell], 1);
    if (pos < BCAP)
        g_ptsB[(size_t)cell * BCAP + pos] = make_float4(x, y, z, __int_as_float(n));
}

// ---------------------------------------------------------------------------
// Transpose features (B, C, N) -> (B, N, C). 64x64 tiles, float4 both ways.
// ---------------------------------------------------------------------------
__global__ void __launch_bounds__(256) transpose_feat(const float* __restrict__ f) {
    __shared__ float tile[64][65];
    int b  = blockIdx.y;
    int n0 = blockIdx.x * 64;
    const float* fb = f + (size_t)b * PC * PN;
    float4*     ftb = g_featT4 + (size_t)b * PN * (PC / 4);
    int t  = threadIdx.x;
    int qd = t & 15;
    int r0 = t >> 4;
#pragma unroll
    for (int k = 0; k < 4; k++) {
        int c = r0 + k * 16;
        float4 v = *(const float4*)(fb + (size_t)c * PN + n0 + qd * 4);
        tile[c][qd * 4 + 0] = v.x;
        tile[c][qd * 4 + 1] = v.y;
        tile[c][qd * 4 + 2] = v.z;
        tile[c][qd * 4 + 3] = v.w;
    }
    __syncthreads();
#pragma unroll
    for (int k = 0; k < 4; k++) {
        int n = r0 + k * 16;
        float4 v;
        v.x = tile[qd * 4 + 0][n];
        v.y = tile[qd * 4 + 1][n];
        v.z = tile[qd * 4 + 2][n];
        v.w = tile[qd * 4 + 3][n];
        ftb[(size_t)(n0 + n) * (PC / 4) + qd] = v;
    }
}

// ---------------------------------------------------------------------------
// Fused ball query + gather + write. One block = 4 queries = 132 output cols.
// Warps 0-3: ball query (dense bucket packing, rank-select). All 8 warps:
// gather feature rows + write 70 channels. Tail re-zeroes g_cellCnt.
// ---------------------------------------------------------------------------
__global__ void __launch_bounds__(256) fused_ball_gather(
    const float* __restrict__ xyz, const float* __restrict__ new_xyz,
    const int* __restrict__ fps, float* __restrict__ out)
{
    __shared__ float tile[TJ][PC + 1];   // [j][c], pitch 65: conflict-free both ways
    __shared__ int   sidx[TJ];           // 4 * 33 selected indices
    __shared__ float sxyz[TJ][3];
    __shared__ float sq[4][3];
    __shared__ int   buf[4][264];
    __shared__ int   scum[4][27];
    __shared__ int   sadj[4][27];

    int bj   = blockIdx.x;               // 0..2047
    int b    = bj / BPBATCH;
    int blkq = bj - b * BPBATCH;         // 0..511
    int j0   = blkq * TJ;
    int tid  = threadIdx.x;
    int w    = tid >> 5;
    int lane = tid & 31;

    // ---- Stage 1: ball query (warps 0-3, one query each) ----
    if (w < 4) {
        int s = blkq * 4 + w;
        const float* q = new_xyz + ((size_t)b * PS + s) * 3;
        float qx = q[0], qy = q[1], qz = q[2];
        if (lane == 0) {
            sq[w][0] = qx; sq[w][1] = qy; sq[w][2] = qz;
            sidx[w * PK] = fps[b * PS + s];
        }

        int cx = min((int)(qx * 10.0f), GR - 1);
        int cy = min((int)(qy * 10.0f), GR - 1);
        int cz = min((int)(qz * 10.0f), GR - 1);
        int* wbuf = buf[w];
        int* cum  = scum[w];
        int* adj  = sadj[w];
        int* outw = sidx + w * PK;

        int z0 = max(cz - 1, 0), z1 = min(cz + 1, GR - 1);
        int y0 = max(cy - 1, 0), y1 = min(cy + 1, GR - 1);
        int x0 = max(cx - 1, 0), x1 = min(cx + 1, GR - 1);

        int nseg = 0, T = 0;
        for (int zz = z0; zz <= z1; zz++) {
            for (int yy = y0; yy <= y1; yy++) {
                int rowbase = b * NC + (zz * GR + yy) * GR;
                for (int xx = x0; xx <= x1; xx++) {
                    int cell = rowbase + xx;
                    int len  = min(g_cellCnt[cell], BCAP);
                    if (len > 0) {
                        if (lane == 0) {
                            adj[nseg] = cell * BCAP - T;
                            cum[nseg] = T + len;
                        }
                        nseg++;
                        T += len;
                    }
                }
            }
        }
        __syncwarp();

        const float R2 = 0.01f;          // (float)(0.1*0.1 in f64) == 0.01f
        const unsigned FULL = 0xffffffffu;
        int cnt = 0;
        int seg = 0;

        for (int base = 0; base < T; base += 32) {
            int idx = base + lane;
            bool hit = false;
            int pid = 0;
            if (idx < T) {
                while (idx >= scum[w][seg]) seg++;
                float4 v = g_ptsB[(size_t)sadj[w][seg] + idx];
                float dx = __fsub_rn(qx, v.x);
                float dy = __fsub_rn(qy, v.y);
                float dz = __fsub_rn(qz, v.z);
                float d2 = __fadd_rn(__fadd_rn(__fmul_rn(dx, dx), __fmul_rn(dy, dy)),
                                     __fmul_rn(dz, dz));
                hit = d2 < R2;
                pid = __float_as_int(v.w);
            }
            unsigned m = __ballot_sync(FULL, hit);
            if (hit) {
                int pos = cnt + __popc(m & ((1u << lane) - 1u));
                if (pos < CAP) wbuf[pos] = pid;
            }
            cnt += __popc(m);
        }

        int M  = min(cnt, CAP);
        int Mp = (M + 3) & ~3;
        if (lane < Mp - M) wbuf[M + lane] = 0x7fffffff;
        __syncwarp();

        int minhit = 0x7fffffff;
        const int4* b4 = (const int4*)wbuf;
        for (int i = lane; i < M; i += 32) {
            int h = wbuf[i];
            minhit = min(minhit, h);
            int rank = 0;
            int nq = Mp >> 2;
            for (int jq = 0; jq < nq; jq++) {
                int4 wv = b4[jq];
                rank += (wv.x < h) + (wv.y < h) + (wv.z < h) + (wv.w < h);
            }
            if (rank < PNS) outw[1 + rank] = h;
        }
#pragma unroll
        for (int off = 16; off; off >>= 1)
            minhit = min(minhit, __shfl_xor_sync(FULL, minhit, off));
        int fill = (cnt == 0) ? 0 : minhit;
        int c = min(cnt, PNS);
        if (lane >= c) outw[1 + lane] = fill;
    }
    __syncthreads();

    // ---- Stage 2: load point xyz for the 132 selected indices ----
    if (tid < TJ) {
        int n = sidx[tid];
        const float* p = xyz + ((size_t)b * PN + n) * 3;
        sxyz[tid][0] = p[0];  sxyz[tid][1] = p[1];  sxyz[tid][2] = p[2];
    }
    __syncthreads();

    // ---- Stage 3: gather feature rows (coalesced 256B row reads) ----
    const float4* ftb = g_featT4 + (size_t)b * PN * (PC / 4);
#pragma unroll
    for (int it = 0; it < 9; it++) {
        int lin = tid + it * 256;
        if (lin < TJ * 16) {
            int jj = lin >> 4;
            int qd = lin & 15;
            float4 v = ftb[(size_t)sidx[jj] * (PC / 4) + qd];
            tile[jj][qd * 4 + 0] = v.x;
            tile[jj][qd * 4 + 1] = v.y;
            tile[jj][qd * 4 + 2] = v.z;
            tile[jj][qd * 4 + 3] = v.w;
        }
    }
    __syncthreads();

    // ---- Stage 4: write 70 channels (scalar stcs, coalesced along j) ----
    float* ob = out + (size_t)b * OUTC * JTOT + j0;

    // xyz channels: warps 0-5 handle channels 0-5 (132 elems each)
    if (w < 6) {
#pragma unroll
        for (int r = 0; r < 5; r++) {
            int jpos = r * 32 + lane;
            if (jpos < TJ) {
                float v;
                if (w < 3) v = sxyz[jpos][w];
                else       v = sxyz[jpos][w - 3] - sq[jpos / PK][w - 3];
                __stcs(&ob[(size_t)w * JTOT + jpos], v);
            }
        }
    }
    // feature channels: 8 iters, channel c = it*8 + w; LDS conflict-free
#pragma unroll
    for (int it = 0; it < 8; it++) {
        int c = it * 8 + w;
#pragma unroll
        for (int r = 0; r < 5; r++) {
            int jpos = r * 32 + lane;
            if (jpos < TJ)
                __stcs(&ob[(size_t)(6 + c) * JTOT + jpos], tile[jpos][c]);
        }
    }

    // Tail: reset cell counters for next replay (after all ball reads in this
    // block; other blocks read their own cells — reset only touches counters
    // via blocks 0..15, which still ordered AFTER their own stage 1 only.
    // Cross-block safety: counters are read in stage 1 of every block, so the
    // reset must be globally last -> do it only in the last-launched wave via
    // a separate trailing kernel instead. (See reset_counts below.)
}

// Trailing counter reset (strictly after fused kernel completes).
__global__ void __launch_bounds__(256) reset_counts() {
    int i = blockIdx.x * 256 + threadIdx.x;
    if (i < PB * NC) g_cellCnt[i] = 0;
}

// ---------------------------------------------------------------------------
extern "C" void kernel_launch(void* const* d_in, const int* in_sizes, int n_in,
                              void* d_out, int out_size) {
    const float* xyz      = (const float*)d_in[0];
    const float* new_xyz  = (const float*)d_in[1];
    const float* features = (const float*)d_in[2];
    const int*   fps_idx  = (const int*)  d_in[3];
    float* out = (float*)d_out;

    static cudaStream_t sT = nullptr;
    static cudaEvent_t evFork = nullptr, evT = nullptr;
    if (!sT) {
        cudaStreamCreateWithFlags(&sT, cudaStreamNonBlocking);
        cudaEventCreateWithFlags(&evFork, cudaEventDisableTiming);
        cudaEventCreateWithFlags(&evT, cudaEventDisableTiming);
    }

    // Fork: transpose concurrent with bucket scatter
    cudaEventRecord(evFork, 0);
    cudaStreamWaitEvent(sT, evFork, 0);
    {
        dim3 grid(PN / 64, PB);
        transpose_feat<<<grid, 256, 0, sT>>>(features);
    }
    cudaEventRecord(evT, sT);

    // Grid build: single direct-scatter pass
    scatter_direct<<<PB * PN / 256, 256>>>(xyz);

    // Join transpose, then fused ball+gather+write
    cudaStreamWaitEvent(0, evT, 0);
    fused_ball_gather<<<PB * BPBATCH, 256>>>(xyz, new_xyz, fps_idx, out);

    // Reset counters for next graph replay
    reset_counts<<<(PB * NC + 255) / 256, 256>>>();
}

// round 17
// speedup vs baseline: 1.2472x; 1.2472x over previous
#include <cuda_runtime.h>
#include <cstdint>

#define PB 4
#define PN 16384
#define PS 2048
#define PC 64
#define PK 33
#define PNS 32
#define JTOT (PS * PK)        // 67584
#define OUTC (6 + PC)         // 70
#define GR 10
#define NC (GR * GR * GR)     // 1000
#define CAP 256
#define TJ 128
#define BCAP 96               // bucket capacity (Poisson(16.4); P(>96)~1e-18)

__device__ int    g_idx[PB * PS * PK];
__device__ float4 g_featT4[(size_t)PB * PN * PC / 4];
__device__ int    g_cellCnt[PB * NC];                 // zero-init; gather tail re-zeroes
__device__ float4 g_ptsB[(size_t)PB * NC * BCAP];     // padded per-cell buckets

__device__ __forceinline__ int cell_of(float x, float y, float z) {
    int ix = min((int)(x * 10.0f), GR - 1);
    int iy = min((int)(y * 10.0f), GR - 1);
    int iz = min((int)(z * 10.0f), GR - 1);
    return (iz * GR + iy) * GR + ix;
}

// ---------------------------------------------------------------------------
// Hybrid K1: independent-work fusion (no barriers, no streams).
//   blocks 0..255    : bucket scatter (1 pt/thread)
//   blocks 256..1279 : feature transpose, one 64x64 tile each
// ---------------------------------------------------------------------------
__global__ void __launch_bounds__(256) build_and_transpose(
    const float* __restrict__ xyz, const float* __restrict__ features)
{
    __shared__ float tile[64][65];       // used by transpose role only
    int blk = blockIdx.x;
    int t   = threadIdx.x;

    if (blk < 256) {
        // --- scatter role ---
        int i = blk * 256 + t;           // 0..65535
        const float* p = xyz + 3 * (size_t)i;
        float x = p[0], y = p[1], z = p[2];
        int b = i >> 14;
        int n = i & (PN - 1);
        int cell = b * NC + cell_of(x, y, z);
        int pos = atomicAdd(&g_cellCnt[cell], 1);
        if (pos < BCAP)
            g_ptsB[(size_t)cell * BCAP + pos] = make_float4(x, y, z, __int_as_float(n));
        return;
    }

    // --- transpose role ---
    int tt = blk - 256;                  // 0..1023
    int b  = tt >> 8;
    int n0 = (tt & 255) * 64;
    const float* fb = features + (size_t)b * PC * PN;
    float4*     ftb = g_featT4 + (size_t)b * PN * (PC / 4);
    int qd = t & 15;
    int r0 = t >> 4;
#pragma unroll
    for (int k = 0; k < 4; k++) {
        int c = r0 + k * 16;
        float4 v = *(const float4*)(fb + (size_t)c * PN + n0 + qd * 4);
        tile[c][qd * 4 + 0] = v.x;
        tile[c][qd * 4 + 1] = v.y;
        tile[c][qd * 4 + 2] = v.z;
        tile[c][qd * 4 + 3] = v.w;
    }
    __syncthreads();
#pragma unroll
    for (int k = 0; k < 4; k++) {
        int n = r0 + k * 16;
        float4 v;
        v.x = tile[qd * 4 + 0][n];
        v.y = tile[qd * 4 + 1][n];
        v.z = tile[qd * 4 + 2][n];
        v.w = tile[qd * 4 + 3][n];
        ftb[(size_t)(n0 + n) * (PC / 4) + qd] = v;
    }
}

// ---------------------------------------------------------------------------
// Ball query — one warp per query; cell-box distance pruning; dense candidate
// packing over surviving bucket segments; rank-select 32 smallest hit indices.
// ---------------------------------------------------------------------------
__global__ void __launch_bounds__(256) ball_query_grid(const float* __restrict__ new_xyz,
                                                       const int*   __restrict__ fps) {
    __shared__ int buf[8][264];
    __shared__ int scum[8][27];
    __shared__ int sadj[8][27];
    int wi   = threadIdx.x >> 5;
    int lane = threadIdx.x & 31;
    int gw   = blockIdx.x * 8 + wi;
    int b = gw >> 11;
    int s = gw & (PS - 1);

    const float* q = new_xyz + ((size_t)b * PS + s) * 3;
    float qx = q[0], qy = q[1], qz = q[2];
    int* out = g_idx + ((size_t)b * PS + s) * PK;
    if (lane == 0) out[0] = fps[b * PS + s];

    int cx = min((int)(qx * 10.0f), GR - 1);
    int cy = min((int)(qy * 10.0f), GR - 1);
    int cz = min((int)(qz * 10.0f), GR - 1);

    const float4* pts = g_ptsB;
    const int* cnt_arr = g_cellCnt;
    int* wbuf = buf[wi];
    int* cum  = scum[wi];
    int* adj  = sadj[wi];

    int z0 = max(cz - 1, 0), z1 = min(cz + 1, GR - 1);
    int y0 = max(cy - 1, 0), y1 = min(cy + 1, GR - 1);
    int x0 = max(cx - 1, 0), x1 = min(cx + 1, GR - 1);

    // Segment table with conservative cell-box pruning (mind2 is a lower
    // bound on any point distance^2 in the cell; prune only if >= R2).
    int nseg = 0, T = 0;
    for (int zz = z0; zz <= z1; zz++) {
        float gz = fmaxf(fmaxf(zz * 0.1f - qz, qz - (zz + 1) * 0.1f), 0.0f);
        for (int yy = y0; yy <= y1; yy++) {
            float gy = fmaxf(fmaxf(yy * 0.1f - qy, qy - (yy + 1) * 0.1f), 0.0f);
            float gzy = gz * gz + gy * gy;
            int rowbase = b * NC + (zz * GR + yy) * GR;
            for (int xx = x0; xx <= x1; xx++) {
                float gx = fmaxf(fmaxf(xx * 0.1f - qx, qx - (xx + 1) * 0.1f), 0.0f);
                if (gzy + gx * gx >= 0.0100001f) continue;   // provably no hits
                int cell = rowbase + xx;
                int len  = min(cnt_arr[cell], BCAP);
                if (len > 0) {
                    if (lane == 0) {
                        adj[nseg] = cell * BCAP - T;
                        cum[nseg] = T + len;
                    }
                    nseg++;
                    T += len;
                }
            }
        }
    }
    __syncwarp();

    const float R2 = 0.01f;   // (float)(0.1*0.1 in f64) == 0.01f
    const unsigned FULL = 0xffffffffu;
    int cnt = 0;
    int seg = 0;

    for (int base = 0; base < T; base += 32) {
        int idx = base + lane;
        bool hit = false;
        int pid = 0;
        if (idx < T) {
            while (idx >= cum[seg]) seg++;
            float4 v = pts[(size_t)adj[seg] + idx];
            float dx = __fsub_rn(qx, v.x);
            float dy = __fsub_rn(qy, v.y);
            float dz = __fsub_rn(qz, v.z);
            float d2 = __fadd_rn(__fadd_rn(__fmul_rn(dx, dx), __fmul_rn(dy, dy)),
                                 __fmul_rn(dz, dz));
            hit = d2 < R2;
            pid = __float_as_int(v.w);
        }
        unsigned m = __ballot_sync(FULL, hit);
        if (hit) {
            int pos = cnt + __popc(m & ((1u << lane) - 1u));
            if (pos < CAP) wbuf[pos] = pid;
        }
        cnt += __popc(m);
    }

    int M  = min(cnt, CAP);
    int Mp = (M + 3) & ~3;
    if (lane < Mp - M) wbuf[M + lane] = 0x7fffffff;
    __syncwarp();

    int minhit = 0x7fffffff;
    const int4* b4 = (const int4*)wbuf;
    for (int i = lane; i < M; i += 32) {
        int h = wbuf[i];
        minhit = min(minhit, h);
        int rank = 0;
        int nq = Mp >> 2;
        for (int j = 0; j < nq; j++) {
            int4 w = b4[j];
            rank += (w.x < h) + (w.y < h) + (w.z < h) + (w.w < h);
        }
        if (rank < PNS) out[1 + rank] = h;
    }
#pragma unroll
    for (int off = 16; off; off >>= 1)
        minhit = min(minhit, __shfl_xor_sync(FULL, minhit, off));
    int fill = (cnt == 0) ? 0 : minhit;
    int c = min(cnt, PNS);
    if (lane >= c) out[1 + lane] = fill;
}

// ---------------------------------------------------------------------------
// Gather + write (R13/R8 version) + tail: reset g_cellCnt for next replay.
// ---------------------------------------------------------------------------
__global__ void __launch_bounds__(256) gather_write(const float* __restrict__ xyz,
                                                    const float* __restrict__ new_xyz,
                                                    float* __restrict__ out) {
    __shared__ float tile[TJ][PC + 1];
    __shared__ int   sn[TJ];
    __shared__ float sxyz[TJ][3];
    __shared__ float sq[TJ][3];

    int bj  = blockIdx.x;
    int b   = bj / (JTOT / TJ);
    int j0  = (bj - b * (JTOT / TJ)) * TJ;
    int tid = threadIdx.x;

    if (tid < TJ) {
        int j = j0 + tid;
        int n = g_idx[(size_t)b * JTOT + j];
        sn[tid] = n;
        const float* p = xyz + ((size_t)b * PN + n) * 3;
        sxyz[tid][0] = p[0];  sxyz[tid][1] = p[1];  sxyz[tid][2] = p[2];
    } else {
        int jt = tid - TJ;
        int s  = (j0 + jt) / PK;
        const float* qp = new_xyz + ((size_t)b * PS + s) * 3;
        sq[jt][0] = qp[0];  sq[jt][1] = qp[1];  sq[jt][2] = qp[2];
    }
    __syncthreads();

    const float4* ftb = g_featT4 + (size_t)b * PN * (PC / 4);
#pragma unroll
    for (int it = 0; it < 8; it++) {
        int lin = tid + it * 256;
        int jj  = lin >> 4;
        int qd  = lin & 15;
        float4 v = ftb[(size_t)sn[jj] * (PC / 4) + qd];
        tile[jj][qd * 4 + 0] = v.x;
        tile[jj][qd * 4 + 1] = v.y;
        tile[jj][qd * 4 + 2] = v.z;
        tile[jj][qd * 4 + 3] = v.w;
    }
    __syncthreads();

    float* ob = out + (size_t)b * OUTC * JTOT + j0;
#pragma unroll
    for (int it = 0; it < 3; it++) {
        int idx  = it * 256 + tid;
        int c    = idx >> 7;
        int jpos = idx & (TJ - 1);
        float v = (c < 3) ? sxyz[jpos][c] : (sxyz[jpos][c - 3] - sq[jpos][c - 3]);
        __stcs(&ob[(size_t)c * JTOT + jpos], v);
    }
#pragma unroll
    for (int it = 0; it < 32; it++) {
        int idx  = it * 256 + tid;
        int c    = idx >> 7;
        int jpos = idx & (TJ - 1);
        __stcs(&ob[(size_t)(6 + c) * JTOT + jpos], tile[jpos][c]);
    }

    // Tail: reset cell counters for the next replay (strictly after
    // ball_query_grid's reads — same-stream kernel ordering).
    if (bj < 16) {
        int i = bj * 256 + tid;
        if (i < PB * NC) g_cellCnt[i] = 0;
    }
}

// ---------------------------------------------------------------------------
extern "C" void kernel_launch(void* const* d_in, const int* in_sizes, int n_in,
                              void* d_out, int out_size) {
    const float* xyz      = (const float*)d_in[0];
    const float* new_xyz  = (const float*)d_in[1];
    const float* features = (const float*)d_in[2];
    const int*   fps_idx  = (const int*)  d_in[3];
    float* out = (float*)d_out;

    // K1: scatter + transpose (independent work, one launch, no streams)
    build_and_transpose<<<256 + PB * (PN / 64), 256>>>(xyz, features);

    // K2: ball query (with cell-box pruning)
    ball_query_grid<<<PB * PS / 8, 256>>>(new_xyz, fps_idx);

    // K3: gather + write (+ counter reset tail)
    gather_write<<<PB * (JTOT / TJ), 256>>>(xyz, new_xyz, out);
}